// round 15
// baseline (speedup 1.0000x reference)
#include <cuda_runtime.h>
#include <cuda_fp16.h>
#include <cstdint>

// ---------------- problem constants ----------------
constexpr int T    = 48;     // Tm1
constexpr int R    = 8;      // rows per CTA
constexpr int NT   = 512;    // threads per CTA
constexpr int NCTA = 8192 / R;   // 1024

// ---------------- device scratch: prepped weight fragments ----------------
__device__ uint2 g_WhhFrag[16384];   // [(nt*8+kc)*32+lane] m16n8k16 B frags of Whh
__device__ uint2 g_W1Frag[8192];     // [(w*16+kc)*32+lane] Wd|Wc frags
__device__ uint2 g_WxFrag[4096];     // [(w*8+kc)*32+lane]  Wx frags (phase 0)

// ---------------- helpers ----------------
__device__ __forceinline__ __half2 u2h2(uint32_t u) { return *reinterpret_cast<__half2*>(&u); }
__device__ __forceinline__ void mma16816(float& d0, float& d1, float& d2, float& d3,
                                         uint32_t a0, uint32_t a2,
                                         uint32_t b0, uint32_t b1) {
    asm volatile(
        "mma.sync.aligned.m16n8k16.row.col.f32.f16.f16.f32 "
        "{%0,%1,%2,%3}, {%4,%5,%6,%7}, {%8,%9}, {%0,%1,%2,%3};\n"
        : "+f"(d0), "+f"(d1), "+f"(d2), "+f"(d3)
        : "r"(a0), "r"(0u), "r"(a2), "r"(0u), "r"(b0), "r"(b1));
}
__device__ __forceinline__ void mma16816_full(float& d0, float& d1, float& d2, float& d3,
                                              uint32_t a0, uint32_t a1, uint32_t a2, uint32_t a3,
                                              uint32_t b0, uint32_t b1) {
    asm volatile(
        "mma.sync.aligned.m16n8k16.row.col.f32.f16.f16.f32 "
        "{%0,%1,%2,%3}, {%4,%5,%6,%7}, {%8,%9}, {%0,%1,%2,%3};\n"
        : "+f"(d0), "+f"(d1), "+f"(d2), "+f"(d3)
        : "r"(a0), "r"(a1), "r"(a2), "r"(a3), "r"(b0), "r"(b1));
}
__device__ __forceinline__ float warp_sum(float v) {
#pragma unroll
    for (int o = 16; o; o >>= 1) v += __shfl_xor_sync(0xffffffffu, v, o);
    return v;
}
__device__ __forceinline__ __half2 tanh2_fast(__half2 x) {   // MUFU.TANH f16x2
    uint32_t xi = *reinterpret_cast<uint32_t*>(&x);
    uint32_t yi;
    asm("tanh.approx.f16x2 %0, %1;" : "=r"(yi) : "r"(xi));
    return *reinterpret_cast<__half2*>(&yi);
}
__device__ __forceinline__ float2 tanh2f(float a, float b) { // pack->tanh2->unpack
    __half2 h = tanh2_fast(__floats2half2_rn(a, b));
    return __half22float2(h);
}
__device__ __forceinline__ float2 sigm2f(float a, float b) { // sigmoid pair via tanh2
    float2 t = tanh2f(0.5f * a, 0.5f * b);
    return make_float2(fmaf(t.x, 0.5f, 0.5f), fmaf(t.y, 0.5f, 0.5f));
}
__device__ __forceinline__ float tanh_acc(float x) {
    float e = __expf(2.0f * x);
    return 1.0f - __fdividef(2.0f, e + 1.0f);
}
__device__ __forceinline__ float sigm(float x) {
    return __fdividef(1.0f, 1.0f + __expf(-x));
}
__device__ __forceinline__ uint32_t pack_h2(float a, float b) {
    __half2 h = __floats2half2_rn(a, b);
    return *reinterpret_cast<uint32_t*>(&h);
}

// ---------------- prep: fragment packing ----------------
__global__ void prep_kernel(const float* __restrict__ W1, const float* __restrict__ Whh) {
    int idx = blockIdx.x * blockDim.x + threadIdx.x;
    if (idx < 16384) {  // Whh B-fragments
        int lane = idx & 31, kc = (idx >> 5) & 7, nt = idx >> 8;
        int n = nt * 8 + (lane >> 2);
        int k0 = kc * 16 + (lane & 3) * 2;
        const float* wr = Whh + n * 128;
        g_WhhFrag[idx] = make_uint2(pack_h2(wr[k0], wr[k0 + 1]),
                                    pack_h2(wr[k0 + 8], wr[k0 + 9]));
    }
    if (idx < 8192) {   // W1 (Wd|Wc) B-fragments
        int lane = idx & 31, kc = (idx >> 5) & 15, w = idx >> 9;
        int j = w * 8 + (lane >> 2);
        int k0 = kc * 16 + (lane & 3) * 2;
        const float* wr = W1 + j * 384;
        g_W1Frag[idx] = make_uint2(pack_h2(wr[k0], wr[k0 + 1]),
                                   pack_h2(wr[k0 + 8], wr[k0 + 9]));
    }
    if (idx < 4096) {   // Wx B-fragments (phase 0)
        int lane = idx & 31, kc = (idx >> 5) & 7, w = idx >> 8;
        int j = w * 8 + (lane >> 2);
        int k0 = kc * 16 + (lane & 3) * 2;
        const float* wr = W1 + j * 384 + 256;
        g_WxFrag[idx] = make_uint2(pack_h2(wr[k0], wr[k0 + 1]),
                                   pack_h2(wr[k0 + 8], wr[k0 + 9]));
    }
}

// ---------------- GRU + linear side branch: out[b] = s_skip + s_linear ----------------
__global__ __launch_bounds__(128) void gru_kernel(
    const float* __restrict__ y_skip, const float* __restrict__ y_prev,
    const float* __restrict__ gWih, const float* __restrict__ gWhh,
    const float* __restrict__ gbih, const float* __restrict__ gbhh,
    const float* __restrict__ l1W, const float* __restrict__ l1b,
    const float* __restrict__ l2W, const float* __restrict__ l2b,
    float* __restrict__ out)
{
    __shared__ float s[200];
    int tid = threadIdx.x;
    for (int i = tid; i < 15; i += 128) { s[i] = gWih[i]; s[96 + i] = gbih[i]; s[112 + i] = gbhh[i]; }
    for (int i = tid; i < 75; i += 128) s[16 + i] = gWhh[i];
    for (int i = tid; i < 5;  i += 128) s[128 + i] = l1W[i];
    for (int i = tid; i < 48; i += 128) s[144 + i] = l2W[i];
    if (tid == 0) { s[192] = l1b[0]; s[193] = l2b[0]; }
    __syncthreads();

    int b = blockIdx.x * 128 + tid;
    float h[5] = {0.f, 0.f, 0.f, 0.f, 0.f};
#pragma unroll 1
    for (int t = 0; t < 24; t++) {
        float x = y_skip[b * 24 + t];
        float gh[15];
#pragma unroll
        for (int jj = 0; jj < 15; jj++) {
            float a = s[112 + jj];
#pragma unroll
            for (int k = 0; k < 5; k++) a += s[16 + jj * 5 + k] * h[k];
            gh[jj] = a;
        }
#pragma unroll
        for (int q = 0; q < 5; q++) {
            float rr = sigm(s[q] * x + s[96 + q] + gh[q]);
            float zz = sigm(s[5 + q] * x + s[101 + q] + gh[5 + q]);
            float nn = tanh_acc(s[10 + q] * x + s[106 + q] + rr * gh[10 + q]);
            h[q] = (1.0f - zz) * nn + zz * h[q];
        }
    }
    float acc = s[192];
#pragma unroll
    for (int q = 0; q < 5; q++) acc += h[q] * s[128 + q];
    float s2 = s[193];
#pragma unroll 8
    for (int t = 0; t < 48; t++) s2 += y_prev[(size_t)b * 48 + t] * s[144 + t];
    out[b] = acc + s2;
}

// ---------------- SMEM layout (byte offsets) ----------------
constexpr int XS_S   = 136;                 // XS half stride (ldmatrix conflict-free)
constexpr int XW_S   = 130;                 // XW half stride (odd word stride: conflict-free)
constexpr int DH_S   = 136;                 // DH/CH half stride: bank (4g+tg)%32 conflict-free
constexpr int GS_S   = 520;                 // GS half stride: word 260g -> conflict-free
constexpr int DP_S   = 136;                 // DP half stride: 272B rows, 16B-aligned
constexpr int OB_XS  = 0;                   // half  [R*T*136]   -> 104448
constexpr int OB_XW  = 104448;              // half  [R*T*130]   -> 204288
constexpr int OB_CS  = 204288;              // float [R*128]     -> 208384
constexpr int OB_DH  = 208384;              // half  [R*136]     -> 210560
constexpr int OB_CH  = 210560;              // half  [R*136]     -> 212736
constexpr int OB_GS  = 212736;              // half  [R*520]     -> 221056 (CT alias GS+4096)
constexpr int OB_DP  = 221056;              // half  [R*136]     -> 223232
constexpr int OB_EB2 = 223232;              // float2[R*T]       -> 226304  (exp, exp*FX)
constexpr int OB_FX  = 226304;              // half  [R*T]       -> 227072
constexpr int OB_YP  = 227072;              // half  [R*T]       -> 227840
constexpr int OB_YT  = 227840;              // float [8]         -> 227872
constexpr int OB_W2  = 227872;              // half  [128]       -> 228128 (16B aligned)
constexpr int OB_B1  = 228128;              // half  [128]       -> 228384
constexpr int OB_WIH = 228384;              // half  [512]       -> 229408
constexpr int OB_BIA = 229408;              // half  [512]       -> 230432
constexpr int OB_FCW = 230432;              // float [130]       -> 230952
constexpr int OB_FCF = 230952;              // float [257]       -> 231980
constexpr int SMEM_BYTES = 231980;          // <= 232448 cap

// ---------------- main persistent decoder ----------------
__global__ __launch_bounds__(NT, 1) void decoder_kernel(
    const float* __restrict__ X, const float* __restrict__ yprev,
    const float* __restrict__ ab1, const float* __restrict__ aW2,
    const float* __restrict__ lWih, const float* __restrict__ lbih, const float* __restrict__ lbhh,
    const float* __restrict__ fcW, const float* __restrict__ fcb,
    const float* __restrict__ fcfW, const float* __restrict__ fcfb,
    float* __restrict__ out)
{
    extern __shared__ char smraw[];
    __half* XS = (__half*)(smraw + OB_XS);
    __half* XW = (__half*)(smraw + OB_XW);
    float*  CS = (float*)(smraw + OB_CS);
    __half* DH = (__half*)(smraw + OB_DH);
    __half* CH = (__half*)(smraw + OB_CH);
    __half* GS = (__half*)(smraw + OB_GS);
    __half* DP = (__half*)(smraw + OB_DP);
    __half* CT = (__half*)(smraw + OB_GS + 4096);  // epilogue-only alias
    float2* EB2 = (float2*)(smraw + OB_EB2);
    __half* FXh = (__half*)(smraw + OB_FX);
    __half* YPh = (__half*)(smraw + OB_YP);
    float*  YT = (float*)(smraw + OB_YT);
    __half* W2h = (__half*)(smraw + OB_W2);
    __half* B1h = (__half*)(smraw + OB_B1);
    __half* WIHh = (__half*)(smraw + OB_WIH);
    __half* BIAh = (__half*)(smraw + OB_BIA);
    float*  FCW = (float*)(smraw + OB_FCW);
    float*  FCF = (float*)(smraw + OB_FCF);

    const int tid  = threadIdx.x;
    const int b0   = blockIdx.x * R;
    const int w    = tid >> 5;        // warp 0..15
    const int lane = tid & 31;
    const int g    = lane >> 2;       // MMA row group 0..7
    const int tg   = lane & 3;        // thread-in-group

    // ---- stage X (fp32 -> fp16, stride 136), smalls, y_prev, zero states ----
    {
        const float2* src = reinterpret_cast<const float2*>(X + (size_t)b0 * T * 128);
        for (int i = tid; i < R * T * 64; i += NT) {
            float2 v = src[i];
            *reinterpret_cast<__half2*>(XS + (i >> 6) * XS_S + (i & 63) * 2) =
                __floats2half2_rn(v.x, v.y);
        }
    }
    for (int i = tid; i < 128; i += NT) { W2h[i] = __float2half(aW2[i]); B1h[i] = __float2half(ab1[i]); }
    for (int i = tid; i < 512; i += NT) {
        WIHh[i] = __float2half(lWih[i]);
        BIAh[i] = __float2half(lbih[i] + lbhh[i]);
    }
    for (int i = tid; i < 129; i += NT) FCW[i] = fcW[i];
    for (int i = tid; i < 256; i += NT) FCF[i] = fcfW[i];
    if (tid == 0) { FCW[129] = fcb[0]; FCF[256] = fcfb[0]; }
    for (int i = tid; i < R * T; i += NT) {
        int r = i / T, tt = i % T;
        YPh[i] = __float2half(yprev[(size_t)(b0 + r) * T + tt]);
    }
    for (int i = tid; i < R * 128; i += NT) {
        int r = i >> 7, q = i & 127;
        CS[i] = 0.0f;
        DH[r * DH_S + q] = __float2half(0.f);
        CH[r * DH_S + q] = __float2half(0.f);
    }
    __syncthreads();

    // ---- phase 0 (MMA): XW[p][j] = sum_k X[p][k]*Wx[k][j] (stride-130 rows) ----
    {
        uint2 bx[8];
#pragma unroll
        for (int kc = 0; kc < 8; ++kc) bx[kc] = g_WxFrag[(w * 8 + kc) * 32 + lane];
        const int rrow = lane & 15;
        const int rcol = (lane >> 4) * 8;
#pragma unroll 1
        for (int mt = 0; mt < 24; ++mt) {
            float c0 = 0.f, c1 = 0.f, c2 = 0.f, c3 = 0.f;
#pragma unroll
            for (int kc = 0; kc < 8; ++kc) {
                uint32_t a0, a1, a2, a3;
                uint32_t addr = static_cast<uint32_t>(
                    __cvta_generic_to_shared(XS + (mt * 16 + rrow) * XS_S + kc * 16 + rcol));
                asm volatile("ldmatrix.sync.aligned.m8n8.x4.shared.b16 {%0,%1,%2,%3}, [%4];"
                             : "=r"(a0), "=r"(a1), "=r"(a2), "=r"(a3) : "r"(addr));
                mma16816_full(c0, c1, c2, c3, a0, a1, a2, a3, bx[kc].x, bx[kc].y);
            }
            int p0 = mt * 16 + g, p1 = p0 + 8;
            int j = w * 8 + tg * 2;
            *reinterpret_cast<__half2*>(XW + p0 * XW_S + j) = __floats2half2_rn(c0, c1);
            *reinterpret_cast<__half2*>(XW + p1 * XW_S + j) = __floats2half2_rn(c2, c3);
        }
    }

    // ---- FX[p] = fc_W . X[p] (y_tilde folding) ----
    if (tid < R * T) {
        float a = 0.f;
        const __half2* xr = reinterpret_cast<const __half2*>(XS + tid * XS_S);
#pragma unroll 8
        for (int k2 = 0; k2 < 64; ++k2) {
            float2 v = __half22float2(xr[k2]);
            a = fmaf(FCW[2 * k2], v.x, fmaf(FCW[2 * k2 + 1], v.y, a));
        }
        FXh[tid] = __float2half(a);
    }

    // ---- preload Whh B-fragments (step-invariant, 64 regs) ----
    uint2 bD[32];
    {
        const uint2* src = g_WhhFrag + (size_t)w * 32 * 32 + lane;
#pragma unroll
        for (int i = 0; i < 32; ++i) bD[i] = src[i * 32];
    }
    __syncthreads();

    // ---- hoist step-invariant per-thread constants ----
    // M-phase biases
    float2 b1v, biav[4];
    {
        int j = w * 8 + tg * 2;
        b1v = __half22float2(*reinterpret_cast<const __half2*>(B1h + j));
#pragma unroll
        for (int ti = 0; ti < 4; ++ti) {
            int jj = (w * 4 + ti) * 8 + tg * 2;
            biav[ti] = __half22float2(*reinterpret_cast<const __half2*>(BIAh + jj));
        }
    }
    // E-phase per-thread WIH and fc scalars
    const int eq0 = (tid & 63) * 2;
    const int er  = tid >> 6;
    float2 wi_i = __half22float2(*reinterpret_cast<const __half2*>(WIHh + eq0));
    float2 wi_f = __half22float2(*reinterpret_cast<const __half2*>(WIHh + 128 + eq0));
    float2 wi_g = __half22float2(*reinterpret_cast<const __half2*>(WIHh + 256 + eq0));
    float2 wi_o = __half22float2(*reinterpret_cast<const __half2*>(WIHh + 384 + eq0));
    const float fcw128 = FCW[128], fcw129 = FCW[129];

    // ---- main recurrence (3 barriers/step) ----
#pragma unroll 1
    for (int t = 0; t < T; ++t) {
        // M: A1-MMA (-> DP, two 8-deep chains) and D-MMA partial (-> GS)
        {
            float c0 = 0.f, c1 = 0.f, c2 = 0.f, c3 = 0.f;   // A1 chain 1 (DH)
            float e0 = 0.f, e1 = 0.f, e2 = 0.f, e3 = 0.f;   // A1 chain 2 (CH)
            float acc[4][4];
#pragma unroll
            for (int ti = 0; ti < 4; ++ti)
#pragma unroll
                for (int q = 0; q < 4; ++q) acc[ti][q] = 0.f;
#pragma unroll
            for (int kc = 0; kc < 8; ++kc) {
                const __half* base = DH + g * DH_S + kc * 16 + tg * 2;
                uint32_t a0 = *reinterpret_cast<const uint32_t*>(base);
                uint32_t a2 = *reinterpret_cast<const uint32_t*>(base + 8);
                uint2 bf = g_W1Frag[(w * 16 + kc) * 32 + lane];
                mma16816(c0, c1, c2, c3, a0, a2, bf.x, bf.y);
#pragma unroll
                for (int ti = 0; ti < 4; ++ti)
                    mma16816(acc[ti][0], acc[ti][1], acc[ti][2], acc[ti][3],
                             a0, a2, bD[ti * 8 + kc].x, bD[ti * 8 + kc].y);
            }
#pragma unroll
            for (int kc = 0; kc < 8; ++kc) {
                const __half* base = CH + g * DH_S + kc * 16 + tg * 2;
                uint32_t a0 = *reinterpret_cast<const uint32_t*>(base);
                uint32_t a2 = *reinterpret_cast<const uint32_t*>(base + 8);
                uint2 bf = g_W1Frag[(w * 16 + 8 + kc) * 32 + lane];
                mma16816(e0, e1, e2, e3, a0, a2, bf.x, bf.y);
            }
            {
                int j = w * 8 + tg * 2;
                *reinterpret_cast<__half2*>(DP + g * DP_S + j) =
                    __floats2half2_rn(c0 + e0 + b1v.x, c1 + e1 + b1v.y);
            }
#pragma unroll
            for (int ti = 0; ti < 4; ++ti) {
                int jj = (w * 4 + ti) * 8 + tg * 2;
                *reinterpret_cast<__half2*>(GS + g * GS_S + jj) =
                    __floats2half2_rn(acc[ti][0] + biav[ti].x, acc[ti][1] + biav[ti].y);
            }
        }
        __syncthreads();
        // B: e[p] = sum_j W2[j]*tanh(DP[r][j]+XW[p][j])
        //    xw: LDS.32 conflict-free; dp/w2: LDS.128 broadcast; 2 accumulators
        if (tid < R * T) {
            const int p = tid;
            const int r = (p * 1366) >> 16;  // p / 48 for p < 384
            const __half2* xw2 = reinterpret_cast<const __half2*>(XW + p * XW_S);
            const uint4* dpv = reinterpret_cast<const uint4*>(DP + r * DP_S);
            const uint4* w2v = reinterpret_cast<const uint4*>(W2h);
            float acc0 = 0.f, acc1 = 0.f;
#pragma unroll 4
            for (int j8 = 0; j8 < 16; ++j8) {
                uint4 dv = dpv[j8];
                uint4 wv = w2v[j8];
                __half2 x0 = xw2[4 * j8 + 0];
                __half2 x1 = xw2[4 * j8 + 1];
                __half2 x2 = xw2[4 * j8 + 2];
                __half2 x3 = xw2[4 * j8 + 3];
                float2 f0 = __half22float2(tanh2_fast(__hadd2(x0, u2h2(dv.x))));
                float2 f1 = __half22float2(tanh2_fast(__hadd2(x1, u2h2(dv.y))));
                float2 f2 = __half22float2(tanh2_fast(__hadd2(x2, u2h2(dv.z))));
                float2 f3 = __half22float2(tanh2_fast(__hadd2(x3, u2h2(dv.w))));
                float2 w0 = __half22float2(u2h2(wv.x));
                float2 w1 = __half22float2(u2h2(wv.y));
                float2 w2_ = __half22float2(u2h2(wv.z));
                float2 w3 = __half22float2(u2h2(wv.w));
                acc0 = fmaf(w0.x, f0.x, fmaf(w0.y, f0.y, acc0));
                acc1 = fmaf(w1.x, f1.x, fmaf(w1.y, f1.y, acc1));
                acc0 = fmaf(w2_.x, f2.x, fmaf(w2_.y, f2.y, acc0));
                acc1 = fmaf(w3.x, f3.x, fmaf(w3.y, f3.y, acc1));
            }
            float ex = __expf(acc0 + acc1);       // |e| <= ~6 -> no max needed
            EB2[p] = make_float2(ex, ex * __half2float(FXh[p]));
        }
        __syncthreads();
        // E: per-warp inline softmax-reduction -> y_tilde, then LSTM update
        {
            float se = 0.f, sp = 0.f;
            if (lane < 24) {
                float4 v = reinterpret_cast<const float4*>(EB2 + er * T)[lane];
                se = v.x + v.z;
                sp = v.y + v.w;
            }
#pragma unroll
            for (int o = 16; o; o >>= 1) {
                se += __shfl_xor_sync(0xffffffffu, se, o);
                sp += __shfl_xor_sync(0xffffffffu, sp, o);
            }
            float yt = __fdividef(sp, se)
                     + fcw128 * __half2float(YPh[er * T + t]) + fcw129;
            const __half2* gsr = reinterpret_cast<const __half2*>(GS + er * GS_S);
            float2 g_i = __half22float2(gsr[eq0 >> 1]);
            float2 g_f = __half22float2(gsr[(128 + eq0) >> 1]);
            float2 g_g = __half22float2(gsr[(256 + eq0) >> 1]);
            float2 g_o = __half22float2(gsr[(384 + eq0) >> 1]);
            float gi0 = fmaf(wi_i.x, yt, g_i.x), gi1 = fmaf(wi_i.y, yt, g_i.y);
            float gf0 = fmaf(wi_f.x, yt, g_f.x), gf1 = fmaf(wi_f.y, yt, g_f.y);
            float gg0 = fmaf(wi_g.x, yt, g_g.x), gg1 = fmaf(wi_g.y, yt, g_g.y);
            float go0 = fmaf(wi_o.x, yt, g_o.x), go1 = fmaf(wi_o.y, yt, g_o.y);
            float2 si = sigm2f(gi0, gi1);
            float2 sf = sigm2f(gf0, gf1);
            float2 so = sigm2f(go0, go1);
            float2 tg2 = tanh2f(gg0, gg1);
            float2 cv = *reinterpret_cast<const float2*>(CS + er * 128 + eq0);
            float cn0 = sf.x * cv.x + si.x * tg2.x;
            float cn1 = sf.y * cv.y + si.y * tg2.y;
            *reinterpret_cast<float2*>(CS + er * 128 + eq0) = make_float2(cn0, cn1);
            float2 tc = tanh2f(cn0, cn1);
            *reinterpret_cast<__half2*>(DH + er * DH_S + eq0) =
                __floats2half2_rn(so.x * tc.x, so.y * tc.y);
            *reinterpret_cast<__half2*>(CH + er * DH_S + eq0) =
                __floats2half2_rn(cn0, cn1);
        }
        __syncthreads();
    }

    // ---- epilogue: per-row inv-sums for final beta ----
    if (tid < 256) {
        const int wr = tid >> 5, l = tid & 31;
        float se = 0.f;
        if (l < 24) {
            float4 v = reinterpret_cast<const float4*>(EB2 + wr * T)[l];
            se = v.x + v.z;
        }
        se = warp_sum(se);
        if (l == 0) YT[wr] = __fdividef(1.0f, se);
    }
    __syncthreads();
    // ---- final context: CT[r][k] = inv[r] * sum_tt exp[r][tt] * X[r][tt][k] ----
    {
        const int k = tid & 127, g2 = tid >> 7;  // g2 in 0..3
        float a0 = 0.f, a1 = 0.f;
#pragma unroll 4
        for (int tt = 0; tt < T; ++tt) {
            a0 += EB2[g2 * T + tt].x       * __half2float(XS[(g2 * T + tt) * XS_S + k]);
            a1 += EB2[(g2 + 4) * T + tt].x * __half2float(XS[((g2 + 4) * T + tt) * XS_S + k]);
        }
        CT[g2 * 128 + k]       = __float2half(a0 * YT[g2]);
        CT[(g2 + 4) * 128 + k] = __float2half(a1 * YT[g2 + 4]);
    }
    __syncthreads();
    // ---- final: out += y_pred ----
    if (tid < 256) {
        const int wr = tid >> 5, l = tid & 31;
        float a = 0.f;
#pragma unroll
        for (int q = 0; q < 4; ++q) {
            int k = l + 32 * q;
            a += FCF[k] * __half2float(DH[wr * DH_S + k])
               + FCF[128 + k] * __half2float(CT[wr * 128 + k]);
        }
        a = warp_sum(a);
        if (l == 0) out[b0 + wr] += a + FCF[256];
    }
}

// ---------------- launch ----------------
extern "C" void kernel_launch(void* const* d_in, const int* in_sizes, int n_in,
                              void* d_out, int out_size) {
    const float* X     = (const float*)d_in[0];
    const float* yprev = (const float*)d_in[1];
    const float* yskip = (const float*)d_in[2];
    const float* aW1   = (const float*)d_in[3];
    const float* ab1   = (const float*)d_in[4];
    const float* aW2   = (const float*)d_in[5];
    // d_in[6] = attn_b2 (softmax shift-invariant -> unused)
    const float* lWih  = (const float*)d_in[7];
    const float* lWhh  = (const float*)d_in[8];
    const float* lbih  = (const float*)d_in[9];
    const float* lbhh  = (const float*)d_in[10];
    const float* fcW   = (const float*)d_in[11];
    const float* fcb   = (const float*)d_in[12];
    const float* fcfW  = (const float*)d_in[13];
    const float* fcfb  = (const float*)d_in[14];
    const float* gWih  = (const float*)d_in[15];
    const float* gWhh  = (const float*)d_in[16];
    const float* gbih  = (const float*)d_in[17];
    const float* gbhh  = (const float*)d_in[18];
    const float* l1W   = (const float*)d_in[19];
    const float* l1b   = (const float*)d_in[20];
    const float* l2W   = (const float*)d_in[21];
    const float* l2b   = (const float*)d_in[22];
    float* out = (float*)d_out;

    cudaFuncSetAttribute(decoder_kernel, cudaFuncAttributeMaxDynamicSharedMemorySize, SMEM_BYTES);

    // side branch writes out[b] = s_skip + s_linear
    gru_kernel<<<8192 / 128, 128>>>(yskip, yprev, gWih, gWhh, gbih, gbhh,
                                    l1W, l1b, l2W, l2b, out);
    // weight fragment packing
    prep_kernel<<<64, 256>>>(aW1, lWhh);
    // main decoder adds y_pred into out
    decoder_kernel<<<NCTA, NT, SMEM_BYTES>>>(X, yprev, ab1, aW2,
                                             lWih, lbih, lbhh,
                                             fcW, fcb, fcfW, fcfb, out);
}

// round 16
// speedup vs baseline: 1.0196x; 1.0196x over previous
#include <cuda_runtime.h>
#include <cuda_fp16.h>
#include <cstdint>

// ---------------- problem constants ----------------
constexpr int T    = 48;     // Tm1
constexpr int R    = 8;      // rows per CTA
constexpr int NT   = 512;    // threads per CTA
constexpr int NCTA = 8192 / R;   // 1024

// ---------------- device scratch: prepped weight fragments ----------------
__device__ uint2 g_WhhFrag[16384];   // [(nt*8+kc)*32+lane] m16n8k16 B frags of Whh
__device__ uint2 g_W1Frag[8192];     // [(w*16+kc)*32+lane] Wd|Wc frags
__device__ uint2 g_WxFrag[4096];     // [(w*8+kc)*32+lane]  Wx frags (phase 0)

// ---------------- helpers ----------------
__device__ __forceinline__ void mma16816(float& d0, float& d1, float& d2, float& d3,
                                         uint32_t a0, uint32_t a2,
                                         uint32_t b0, uint32_t b1) {
    asm volatile(
        "mma.sync.aligned.m16n8k16.row.col.f32.f16.f16.f32 "
        "{%0,%1,%2,%3}, {%4,%5,%6,%7}, {%8,%9}, {%0,%1,%2,%3};\n"
        : "+f"(d0), "+f"(d1), "+f"(d2), "+f"(d3)
        : "r"(a0), "r"(0u), "r"(a2), "r"(0u), "r"(b0), "r"(b1));
}
__device__ __forceinline__ void mma16816_full(float& d0, float& d1, float& d2, float& d3,
                                              uint32_t a0, uint32_t a1, uint32_t a2, uint32_t a3,
                                              uint32_t b0, uint32_t b1) {
    asm volatile(
        "mma.sync.aligned.m16n8k16.row.col.f32.f16.f16.f32 "
        "{%0,%1,%2,%3}, {%4,%5,%6,%7}, {%8,%9}, {%0,%1,%2,%3};\n"
        : "+f"(d0), "+f"(d1), "+f"(d2), "+f"(d3)
        : "r"(a0), "r"(a1), "r"(a2), "r"(a3), "r"(b0), "r"(b1));
}
__device__ __forceinline__ float warp_sum(float v) {
#pragma unroll
    for (int o = 16; o; o >>= 1) v += __shfl_xor_sync(0xffffffffu, v, o);
    return v;
}
__device__ __forceinline__ __half2 tanh2_fast(__half2 x) {   // MUFU.TANH f16x2
    uint32_t xi = *reinterpret_cast<uint32_t*>(&x);
    uint32_t yi;
    asm("tanh.approx.f16x2 %0, %1;" : "=r"(yi) : "r"(xi));
    return *reinterpret_cast<__half2*>(&yi);
}
__device__ __forceinline__ float2 tanh2f(float a, float b) { // pack->tanh2->unpack
    __half2 h = tanh2_fast(__floats2half2_rn(a, b));
    return __half22float2(h);
}
__device__ __forceinline__ float2 sigm2f(float a, float b) { // sigmoid pair via tanh2
    float2 t = tanh2f(0.5f * a, 0.5f * b);
    return make_float2(fmaf(t.x, 0.5f, 0.5f), fmaf(t.y, 0.5f, 0.5f));
}
__device__ __forceinline__ float tanh_acc(float x) {
    float e = __expf(2.0f * x);
    return 1.0f - __fdividef(2.0f, e + 1.0f);
}
__device__ __forceinline__ float sigm(float x) {
    return __fdividef(1.0f, 1.0f + __expf(-x));
}
__device__ __forceinline__ uint32_t pack_h2(float a, float b) {
    __half2 h = __floats2half2_rn(a, b);
    return *reinterpret_cast<uint32_t*>(&h);
}

// ---------------- prep: fragment packing ----------------
__global__ void prep_kernel(const float* __restrict__ W1, const float* __restrict__ Whh) {
    int idx = blockIdx.x * blockDim.x + threadIdx.x;
    if (idx < 16384) {  // Whh B-fragments
        int lane = idx & 31, kc = (idx >> 5) & 7, nt = idx >> 8;
        int n = nt * 8 + (lane >> 2);
        int k0 = kc * 16 + (lane & 3) * 2;
        const float* wr = Whh + n * 128;
        g_WhhFrag[idx] = make_uint2(pack_h2(wr[k0], wr[k0 + 1]),
                                    pack_h2(wr[k0 + 8], wr[k0 + 9]));
    }
    if (idx < 8192) {   // W1 (Wd|Wc) B-fragments
        int lane = idx & 31, kc = (idx >> 5) & 15, w = idx >> 9;
        int j = w * 8 + (lane >> 2);
        int k0 = kc * 16 + (lane & 3) * 2;
        const float* wr = W1 + j * 384;
        g_W1Frag[idx] = make_uint2(pack_h2(wr[k0], wr[k0 + 1]),
                                   pack_h2(wr[k0 + 8], wr[k0 + 9]));
    }
    if (idx < 4096) {   // Wx B-fragments (phase 0)
        int lane = idx & 31, kc = (idx >> 5) & 7, w = idx >> 8;
        int j = w * 8 + (lane >> 2);
        int k0 = kc * 16 + (lane & 3) * 2;
        const float* wr = W1 + j * 384 + 256;
        g_WxFrag[idx] = make_uint2(pack_h2(wr[k0], wr[k0 + 1]),
                                   pack_h2(wr[k0 + 8], wr[k0 + 9]));
    }
}

// ---------------- GRU + linear side branch: out[b] = s_skip + s_linear ----------------
__global__ __launch_bounds__(128) void gru_kernel(
    const float* __restrict__ y_skip, const float* __restrict__ y_prev,
    const float* __restrict__ gWih, const float* __restrict__ gWhh,
    const float* __restrict__ gbih, const float* __restrict__ gbhh,
    const float* __restrict__ l1W, const float* __restrict__ l1b,
    const float* __restrict__ l2W, const float* __restrict__ l2b,
    float* __restrict__ out)
{
    __shared__ float s[200];
    int tid = threadIdx.x;
    for (int i = tid; i < 15; i += 128) { s[i] = gWih[i]; s[96 + i] = gbih[i]; s[112 + i] = gbhh[i]; }
    for (int i = tid; i < 75; i += 128) s[16 + i] = gWhh[i];
    for (int i = tid; i < 5;  i += 128) s[128 + i] = l1W[i];
    for (int i = tid; i < 48; i += 128) s[144 + i] = l2W[i];
    if (tid == 0) { s[192] = l1b[0]; s[193] = l2b[0]; }
    __syncthreads();

    int b = blockIdx.x * 128 + tid;
    float h[5] = {0.f, 0.f, 0.f, 0.f, 0.f};
#pragma unroll 1
    for (int t = 0; t < 24; t++) {
        float x = y_skip[b * 24 + t];
        float gh[15];
#pragma unroll
        for (int jj = 0; jj < 15; jj++) {
            float a = s[112 + jj];
#pragma unroll
            for (int k = 0; k < 5; k++) a += s[16 + jj * 5 + k] * h[k];
            gh[jj] = a;
        }
#pragma unroll
        for (int q = 0; q < 5; q++) {
            float rr = sigm(s[q] * x + s[96 + q] + gh[q]);
            float zz = sigm(s[5 + q] * x + s[101 + q] + gh[5 + q]);
            float nn = tanh_acc(s[10 + q] * x + s[106 + q] + rr * gh[10 + q]);
            h[q] = (1.0f - zz) * nn + zz * h[q];
        }
    }
    float acc = s[192];
#pragma unroll
    for (int q = 0; q < 5; q++) acc += h[q] * s[128 + q];
    float s2 = s[193];
#pragma unroll 8
    for (int t = 0; t < 48; t++) s2 += y_prev[(size_t)b * 48 + t] * s[144 + t];
    out[b] = acc + s2;
}

// ---------------- SMEM layout (byte offsets) ----------------
constexpr int XS_S   = 136;                 // XS half stride (ldmatrix conflict-free)
constexpr int XW_S   = 130;                 // XW half stride (odd word stride: conflict-free)
constexpr int DH_S   = 136;                 // DH/CH half stride: bank (4g+tg)%32 conflict-free
constexpr int GS_S   = 520;                 // GS half stride: word 260g -> conflict-free
constexpr int DP_S   = 136;                 // DP half stride: word 68g -> conflict-free
constexpr int OB_XS  = 0;                   // half  [R*T*136]   -> 104448
constexpr int OB_XW  = 104448;              // half  [R*T*130]   -> 204288
constexpr int OB_CS  = 204288;              // float [R*128]     -> 208384
constexpr int OB_DH  = 208384;              // half  [R*136]     -> 210560
constexpr int OB_CH  = 210560;              // half  [R*136]     -> 212736
constexpr int OB_GS  = 212736;              // half  [R*520]     -> 221056 (CT alias GS+4096)
constexpr int OB_DP  = 221056;              // half  [R*136]     -> 223232
constexpr int OB_EB2 = 223232;              // float2[R*T]       -> 226304  (exp, exp*FX)
constexpr int OB_FX  = 226304;              // half  [R*T]       -> 227072
constexpr int OB_YP  = 227072;              // half  [R*T]       -> 227840
constexpr int OB_YT  = 227840;              // float [8]         -> 227872
constexpr int OB_W2  = 227872;              // half  [128]       -> 228128
constexpr int OB_B1  = 228128;              // half  [128]       -> 228384
constexpr int OB_WIH = 228384;              // half  [512]       -> 229408
constexpr int OB_BIA = 229408;              // half  [512]       -> 230432
constexpr int OB_FCW = 230432;              // float [130]       -> 230952
constexpr int OB_FCF = 230952;              // float [257]       -> 231980
constexpr int SMEM_BYTES = 231980;          // <= 232448 cap

// ---------------- main persistent decoder ----------------
__global__ __launch_bounds__(NT, 1) void decoder_kernel(
    const float* __restrict__ X, const float* __restrict__ yprev,
    const float* __restrict__ ab1, const float* __restrict__ aW2,
    const float* __restrict__ lWih, const float* __restrict__ lbih, const float* __restrict__ lbhh,
    const float* __restrict__ fcW, const float* __restrict__ fcb,
    const float* __restrict__ fcfW, const float* __restrict__ fcfb,
    float* __restrict__ out)
{
    extern __shared__ char smraw[];
    __half* XS = (__half*)(smraw + OB_XS);
    __half* XW = (__half*)(smraw + OB_XW);
    float*  CS = (float*)(smraw + OB_CS);
    __half* DH = (__half*)(smraw + OB_DH);
    __half* CH = (__half*)(smraw + OB_CH);
    __half* GS = (__half*)(smraw + OB_GS);
    __half* DP = (__half*)(smraw + OB_DP);
    __half* CT = (__half*)(smraw + OB_GS + 4096);  // epilogue-only alias
    float2* EB2 = (float2*)(smraw + OB_EB2);
    __half* FXh = (__half*)(smraw + OB_FX);
    __half* YPh = (__half*)(smraw + OB_YP);
    float*  YT = (float*)(smraw + OB_YT);
    __half* W2h = (__half*)(smraw + OB_W2);
    __half* B1h = (__half*)(smraw + OB_B1);
    __half* WIHh = (__half*)(smraw + OB_WIH);
    __half* BIAh = (__half*)(smraw + OB_BIA);
    float*  FCW = (float*)(smraw + OB_FCW);
    float*  FCF = (float*)(smraw + OB_FCF);

    const int tid  = threadIdx.x;
    const int b0   = blockIdx.x * R;
    const int w    = tid >> 5;        // warp 0..15
    const int lane = tid & 31;
    const int g    = lane >> 2;       // MMA row group 0..7
    const int tg   = lane & 3;        // thread-in-group

    // ---- stage X (fp32 -> fp16, stride 136), smalls, y_prev, zero states ----
    {
        const float2* src = reinterpret_cast<const float2*>(X + (size_t)b0 * T * 128);
        for (int i = tid; i < R * T * 64; i += NT) {
            float2 v = src[i];
            *reinterpret_cast<__half2*>(XS + (i >> 6) * XS_S + (i & 63) * 2) =
                __floats2half2_rn(v.x, v.y);
        }
    }
    for (int i = tid; i < 128; i += NT) { W2h[i] = __float2half(aW2[i]); B1h[i] = __float2half(ab1[i]); }
    for (int i = tid; i < 512; i += NT) {
        WIHh[i] = __float2half(lWih[i]);
        BIAh[i] = __float2half(lbih[i] + lbhh[i]);
    }
    for (int i = tid; i < 129; i += NT) FCW[i] = fcW[i];
    for (int i = tid; i < 256; i += NT) FCF[i] = fcfW[i];
    if (tid == 0) { FCW[129] = fcb[0]; FCF[256] = fcfb[0]; }
    for (int i = tid; i < R * T; i += NT) {
        int r = i / T, tt = i % T;
        YPh[i] = __float2half(yprev[(size_t)(b0 + r) * T + tt]);
    }
    for (int i = tid; i < R * 128; i += NT) {
        int r = i >> 7, q = i & 127;
        CS[i] = 0.0f;
        DH[r * DH_S + q] = __float2half(0.f);
        CH[r * DH_S + q] = __float2half(0.f);
    }
    __syncthreads();

    // ---- phase 0 (MMA): XW[p][j] = sum_k X[p][k]*Wx[k][j] (stride-130 rows) ----
    {
        uint2 bx[8];
#pragma unroll
        for (int kc = 0; kc < 8; ++kc) bx[kc] = g_WxFrag[(w * 8 + kc) * 32 + lane];
        const int rrow = lane & 15;
        const int rcol = (lane >> 4) * 8;
#pragma unroll 1
        for (int mt = 0; mt < 24; ++mt) {
            float c0 = 0.f, c1 = 0.f, c2 = 0.f, c3 = 0.f;
#pragma unroll
            for (int kc = 0; kc < 8; ++kc) {
                uint32_t a0, a1, a2, a3;
                uint32_t addr = static_cast<uint32_t>(
                    __cvta_generic_to_shared(XS + (mt * 16 + rrow) * XS_S + kc * 16 + rcol));
                asm volatile("ldmatrix.sync.aligned.m8n8.x4.shared.b16 {%0,%1,%2,%3}, [%4];"
                             : "=r"(a0), "=r"(a1), "=r"(a2), "=r"(a3) : "r"(addr));
                mma16816_full(c0, c1, c2, c3, a0, a1, a2, a3, bx[kc].x, bx[kc].y);
            }
            int p0 = mt * 16 + g, p1 = p0 + 8;
            int j = w * 8 + tg * 2;
            *reinterpret_cast<__half2*>(XW + p0 * XW_S + j) = __floats2half2_rn(c0, c1);
            *reinterpret_cast<__half2*>(XW + p1 * XW_S + j) = __floats2half2_rn(c2, c3);
        }
    }

    // ---- FX[p] = fc_W . X[p] (y_tilde folding) ----
    if (tid < R * T) {
        float a = 0.f;
        const __half2* xr = reinterpret_cast<const __half2*>(XS + tid * XS_S);
#pragma unroll 8
        for (int k2 = 0; k2 < 64; ++k2) {
            float2 v = __half22float2(xr[k2]);
            a = fmaf(FCW[2 * k2], v.x, fmaf(FCW[2 * k2 + 1], v.y, a));
        }
        FXh[tid] = __float2half(a);
    }

    // ---- preload Whh B-fragments (step-invariant, 64 regs) ----
    uint2 bD[32];
    {
        const uint2* src = g_WhhFrag + (size_t)w * 32 * 32 + lane;
#pragma unroll
        for (int i = 0; i < 32; ++i) bD[i] = src[i * 32];
    }
    __syncthreads();

    // ---- main recurrence (3 barriers/step) ----
#pragma unroll 1
    for (int t = 0; t < T; ++t) {
        // M: A1-MMA (-> DP, two 8-deep chains) and D-MMA partial (-> GS)
        {
            float c0 = 0.f, c1 = 0.f, c2 = 0.f, c3 = 0.f;   // A1 chain 1 (DH)
            float e0 = 0.f, e1 = 0.f, e2 = 0.f, e3 = 0.f;   // A1 chain 2 (CH)
            float acc[4][4];
#pragma unroll
            for (int ti = 0; ti < 4; ++ti)
#pragma unroll
                for (int q = 0; q < 4; ++q) acc[ti][q] = 0.f;
#pragma unroll
            for (int kc = 0; kc < 8; ++kc) {
                const __half* base = DH + g * DH_S + kc * 16 + tg * 2;
                uint32_t a0 = *reinterpret_cast<const uint32_t*>(base);
                uint32_t a2 = *reinterpret_cast<const uint32_t*>(base + 8);
                uint2 bf = g_W1Frag[(w * 16 + kc) * 32 + lane];
                mma16816(c0, c1, c2, c3, a0, a2, bf.x, bf.y);
#pragma unroll
                for (int ti = 0; ti < 4; ++ti)
                    mma16816(acc[ti][0], acc[ti][1], acc[ti][2], acc[ti][3],
                             a0, a2, bD[ti * 8 + kc].x, bD[ti * 8 + kc].y);
            }
#pragma unroll
            for (int kc = 0; kc < 8; ++kc) {
                const __half* base = CH + g * DH_S + kc * 16 + tg * 2;
                uint32_t a0 = *reinterpret_cast<const uint32_t*>(base);
                uint32_t a2 = *reinterpret_cast<const uint32_t*>(base + 8);
                uint2 bf = g_W1Frag[(w * 16 + 8 + kc) * 32 + lane];
                mma16816(e0, e1, e2, e3, a0, a2, bf.x, bf.y);
            }
            {
                int j = w * 8 + tg * 2;
                float2 b1v = __half22float2(*reinterpret_cast<const __half2*>(B1h + j));
                *reinterpret_cast<__half2*>(DP + g * DP_S + j) =
                    __floats2half2_rn(c0 + e0 + b1v.x, c1 + e1 + b1v.y);
            }
#pragma unroll
            for (int ti = 0; ti < 4; ++ti) {
                int jj = (w * 4 + ti) * 8 + tg * 2;
                float2 bia = __half22float2(*reinterpret_cast<const __half2*>(BIAh + jj));
                *reinterpret_cast<__half2*>(GS + g * GS_S + jj) =
                    __floats2half2_rn(acc[ti][0] + bia.x, acc[ti][1] + bia.y);
            }
        }
        __syncthreads();
        // B: e[p] = sum_j W2[j]*tanh(DP[r][j]+XW[p][j])
        //    scalar conflict-free loads; HFMA2 accumulate, fp32 promote per 8
        if (tid < R * T) {
            const int p = tid;
            const int r = (p * 1366) >> 16;  // p / 48 for p < 384
            const __half2* dp2 = reinterpret_cast<const __half2*>(DP + r * DP_S);
            const __half2* xw2 = reinterpret_cast<const __half2*>(XW + p * XW_S);
            const __half2* w22 = reinterpret_cast<const __half2*>(W2h);
            float accf = 0.f;
#pragma unroll
            for (int blk = 0; blk < 8; ++blk) {
                __half2 a2 = __floats2half2_rn(0.f, 0.f);
#pragma unroll
                for (int q = 0; q < 8; ++q) {
                    int j2 = blk * 8 + q;
                    __half2 s = __hadd2(dp2[j2], xw2[j2]);
                    a2 = __hfma2(w22[j2], tanh2_fast(s), a2);
                }
                float2 f = __half22float2(a2);
                accf += f.x + f.y;
            }
            float ex = __expf(accf);              // |e| <= ~6 -> no max needed
            EB2[p] = make_float2(ex, ex * __half2float(FXh[p]));
        }
        __syncthreads();
        // E: per-warp inline softmax-reduction -> y_tilde, then LSTM update
        {
            const int r = tid >> 6;               // uniform per warp pair
            float se = 0.f, sp = 0.f;
            if (lane < 24) {
                float4 v = reinterpret_cast<const float4*>(EB2 + r * T)[lane];
                se = v.x + v.z;
                sp = v.y + v.w;
            }
#pragma unroll
            for (int o = 16; o; o >>= 1) {
                se += __shfl_xor_sync(0xffffffffu, se, o);
                sp += __shfl_xor_sync(0xffffffffu, sp, o);
            }
            float yt = __fdividef(sp, se)
                     + FCW[128] * __half2float(YPh[r * T + t]) + FCW[129];
            const int q0 = (tid & 63) * 2;
            const __half2* gsr = reinterpret_cast<const __half2*>(GS + r * GS_S);
            float2 wi_i = __half22float2(*reinterpret_cast<const __half2*>(WIHh + q0));
            float2 wi_f = __half22float2(*reinterpret_cast<const __half2*>(WIHh + 128 + q0));
            float2 wi_g = __half22float2(*reinterpret_cast<const __half2*>(WIHh + 256 + q0));
            float2 wi_o = __half22float2(*reinterpret_cast<const __half2*>(WIHh + 384 + q0));
            float2 g_i = __half22float2(gsr[q0 >> 1]);
            float2 g_f = __half22float2(gsr[(128 + q0) >> 1]);
            float2 g_g = __half22float2(gsr[(256 + q0) >> 1]);
            float2 g_o = __half22float2(gsr[(384 + q0) >> 1]);
            float gi0 = fmaf(wi_i.x, yt, g_i.x), gi1 = fmaf(wi_i.y, yt, g_i.y);
            float gf0 = fmaf(wi_f.x, yt, g_f.x), gf1 = fmaf(wi_f.y, yt, g_f.y);
            float gg0 = fmaf(wi_g.x, yt, g_g.x), gg1 = fmaf(wi_g.y, yt, g_g.y);
            float go0 = fmaf(wi_o.x, yt, g_o.x), go1 = fmaf(wi_o.y, yt, g_o.y);
            float2 si = sigm2f(gi0, gi1);
            float2 sf = sigm2f(gf0, gf1);
            float2 so = sigm2f(go0, go1);
            float2 tg2 = tanh2f(gg0, gg1);
            float2 cv = *reinterpret_cast<const float2*>(CS + r * 128 + q0);
            float cn0 = sf.x * cv.x + si.x * tg2.x;
            float cn1 = sf.y * cv.y + si.y * tg2.y;
            *reinterpret_cast<float2*>(CS + r * 128 + q0) = make_float2(cn0, cn1);
            float2 tc = tanh2f(cn0, cn1);
            *reinterpret_cast<__half2*>(DH + r * DH_S + q0) =
                __floats2half2_rn(so.x * tc.x, so.y * tc.y);
            *reinterpret_cast<__half2*>(CH + r * DH_S + q0) =
                __floats2half2_rn(cn0, cn1);
        }
        __syncthreads();
    }

    // ---- epilogue: per-row inv-sums for final beta ----
    if (tid < 256) {
        const int wr = tid >> 5, l = tid & 31;
        float se = 0.f;
        if (l < 24) {
            float4 v = reinterpret_cast<const float4*>(EB2 + wr * T)[l];
            se = v.x + v.z;
        }
        se = warp_sum(se);
        if (l == 0) YT[wr] = __fdividef(1.0f, se);
    }
    __syncthreads();
    // ---- final context: CT[r][k] = inv[r] * sum_tt exp[r][tt] * X[r][tt][k] ----
    {
        const int k = tid & 127, g2 = tid >> 7;  // g2 in 0..3
        float a0 = 0.f, a1 = 0.f;
#pragma unroll 4
        for (int tt = 0; tt < T; ++tt) {
            a0 += EB2[g2 * T + tt].x       * __half2float(XS[(g2 * T + tt) * XS_S + k]);
            a1 += EB2[(g2 + 4) * T + tt].x * __half2float(XS[((g2 + 4) * T + tt) * XS_S + k]);
        }
        CT[g2 * 128 + k]       = __float2half(a0 * YT[g2]);
        CT[(g2 + 4) * 128 + k] = __float2half(a1 * YT[g2 + 4]);
    }
    __syncthreads();
    // ---- final: out += y_pred ----
    if (tid < 256) {
        const int wr = tid >> 5, l = tid & 31;
        float a = 0.f;
#pragma unroll
        for (int q = 0; q < 4; ++q) {
            int k = l + 32 * q;
            a += FCF[k] * __half2float(DH[wr * DH_S + k])
               + FCF[128 + k] * __half2float(CT[wr * 128 + k]);
        }
        a = warp_sum(a);
        if (l == 0) out[b0 + wr] += a + FCF[256];
    }
}

// ---------------- launch ----------------
extern "C" void kernel_launch(void* const* d_in, const int* in_sizes, int n_in,
                              void* d_out, int out_size) {
    const float* X     = (const float*)d_in[0];
    const float* yprev = (const float*)d_in[1];
    const float* yskip = (const float*)d_in[2];
    const float* aW1   = (const float*)d_in[3];
    const float* ab1   = (const float*)d_in[4];
    const float* aW2   = (const float*)d_in[5];
    // d_in[6] = attn_b2 (softmax shift-invariant -> unused)
    const float* lWih  = (const float*)d_in[7];
    const float* lWhh  = (const float*)d_in[8];
    const float* lbih  = (const float*)d_in[9];
    const float* lbhh  = (const float*)d_in[10];
    const float* fcW   = (const float*)d_in[11];
    const float* fcb   = (const float*)d_in[12];
    const float* fcfW  = (const float*)d_in[13];
    const float* fcfb  = (const float*)d_in[14];
    const float* gWih  = (const float*)d_in[15];
    const float* gWhh  = (const float*)d_in[16];
    const float* gbih  = (const float*)d_in[17];
    const float* gbhh  = (const float*)d_in[18];
    const float* l1W   = (const float*)d_in[19];
    const float* l1b   = (const float*)d_in[20];
    const float* l2W   = (const float*)d_in[21];
    const float* l2b   = (const float*)d_in[22];
    float* out = (float*)d_out;

    cudaFuncSetAttribute(decoder_kernel, cudaFuncAttributeMaxDynamicSharedMemorySize, SMEM_BYTES);

    // side branch writes out[b] = s_skip + s_linear
    gru_kernel<<<8192 / 128, 128>>>(yskip, yprev, gWih, gWhh, gbih, gbhh,
                                    l1W, l1b, l2W, l2b, out);
    // weight fragment packing
    prep_kernel<<<64, 256>>>(aW1, lWhh);
    // main decoder adds y_pred into out
    decoder_kernel<<<NCTA, NT, SMEM_BYTES>>>(X, yprev, ab1, aW2,
                                             lWih, lbih, lbhh,
                                             fcW, fcb, fcfW, fcfb, out);
}